// round 3
// baseline (speedup 1.0000x reference)
#include <cuda_runtime.h>
#include <cstdint>

namespace {
constexpr int kB   = 256;
constexpr int kD   = 2048;
constexpr int kS   = 8;
constexpr int kOut = 1000;

constexpr int BM = 32;
constexpr int BN = 128;
constexpr int BK = 16;
constexpr int NSPLIT = 8;
constexpr int KSPLIT = kD / NSPLIT;          // 256
constexpr int MT = 4;                        // covers subject counts up to 128
constexpr int NTILES = (kOut + BN - 1) / BN; // 8
}

// Device scratch (allocations forbidden in kernel_launch)
__device__ float g_partial[NSPLIT * kB * kOut];  // 8 MB

// ---- packed f32x2 helpers (sm_103a FFMA2 — only reachable via PTX) ----
__device__ __forceinline__ unsigned long long pack2(float lo, float hi) {
    unsigned long long r;
    asm("mov.b64 %0, {%1, %2};" : "=l"(r) : "f"(lo), "f"(hi));
    return r;
}
__device__ __forceinline__ void unpack2(unsigned long long v, float& lo, float& hi) {
    asm("mov.b64 {%0, %1}, %2;" : "=f"(lo), "=f"(hi) : "l"(v));
}
__device__ __forceinline__ void ffma2(unsigned long long& d,
                                      unsigned long long a, unsigned long long b) {
    asm("fma.rn.f32x2 %0, %1, %2, %0;" : "+l"(d) : "l"(a), "l"(b));
}

// ---------------------------------------------------------------------------
// GEMM: grid (n_tile, subject, m_tile*split), 128 threads.
// Each block builds its subject's ordered row list via warp-0 ballot
// compaction over the 256 subject ids (no separate bucket kernel).
// int64-vs-int32 id detection: for little-endian int64 ids in [0,8) all odd
// 32-bit words are zero; for int32 the odd words include 128 random ids.
// Inner loop: packed f32x2 FMAs, double-buffered smem, 1 barrier/stage.
// ---------------------------------------------------------------------------
__global__ __launch_bounds__(128) void gemm_kernel(
    const float* __restrict__ x,             // [B, D]
    const float* __restrict__ W,             // [S, D, OUT]
    const unsigned int* __restrict__ sid_words)
{
    const int s     = blockIdx.y;
    const int mt    = blockIdx.z & (MT - 1);
    const int split = blockIdx.z / MT;
    const int m0    = mt * BM;
    const int n0    = blockIdx.x * BN;
    const int kbase = split * KSPLIT;
    const int t     = threadIdx.x;

    __shared__ unsigned long long Xs[2][BK][BM];   // duplicated {v,v} pairs
    __shared__ float Ws[2][BK][BN];
    __shared__ int   srows[BM];
    __shared__ int   cnt_sh;

    if (t < BM) srows[t] = -1;
    __syncthreads();

    if (t < 32) {
        const unsigned full = 0xFFFFFFFFu;
        unsigned any_hi = 0;
        #pragma unroll
        for (int c = 0; c < 4; ++c) any_hi |= sid_words[2 * (c * 32 + t) + 1];
        const bool is_i32 = __any_sync(full, any_hi != 0u);
        int base = 0;
        #pragma unroll
        for (int c = 0; c < 8; ++c) {
            const int b  = c * 32 + t;
            const int sb = is_i32 ? (int)sid_words[b] : (int)sid_words[2 * b];
            const unsigned m = __ballot_sync(full, sb == s);
            if (sb == s) {
                const int pos = base + __popc(m & ((1u << t) - 1u));
                if (pos >= m0 && pos < m0 + BM) srows[pos - m0] = b;
            }
            base += __popc(m);
        }
        if (t == 0) cnt_sh = base;
    }
    __syncthreads();
    if (m0 >= cnt_sh) return;   // uniform per block; no further barriers if taken

    // ---- global-load roles ----
    const int xm = t & 31;
    const int xk = (t >> 5) * 4;
    const int xrow = srows[xm];
    const float* xptr = (xrow >= 0) ? (x + (size_t)xrow * kD + xk) : nullptr;

    const int wn = (t & 31) * 4;
    const int wk = t >> 5;
    const float* wptr = W + (size_t)s * kD * kOut + n0 + wn;
    const bool w_full = (n0 + wn + 3) < kOut;

    // ---- compute roles: rows [tm, tm+4), col pairs starting at tn ----
    const int ty = t >> 4;
    const int tx = t & 15;
    const int tm = ty * 4;
    const int tn = tx * 8;

    unsigned long long acc[4][4];
    #pragma unroll
    for (int i = 0; i < 4; ++i)
        #pragma unroll
        for (int j = 0; j < 4; ++j) acc[i][j] = 0ull;   // {0.f, 0.f}

    float4 xr;
    float4 wr[4];
    auto load_stage = [&](int k0) {
        xr = xptr ? *reinterpret_cast<const float4*>(xptr + k0)
                  : make_float4(0.f, 0.f, 0.f, 0.f);
        #pragma unroll
        for (int q = 0; q < 4; ++q) {
            const float* wp = wptr + (size_t)(k0 + wk + q * 4) * kOut;
            if (w_full) {
                wr[q] = *reinterpret_cast<const float4*>(wp);
            } else {
                wr[q].x = (n0 + wn + 0 < kOut) ? wp[0] : 0.f;
                wr[q].y = (n0 + wn + 1 < kOut) ? wp[1] : 0.f;
                wr[q].z = (n0 + wn + 2 < kOut) ? wp[2] : 0.f;
                wr[q].w = (n0 + wn + 3 < kOut) ? wp[3] : 0.f;
            }
        }
    };
    auto commit = [&](int p) {
        Xs[p][xk + 0][xm] = pack2(xr.x, xr.x);
        Xs[p][xk + 1][xm] = pack2(xr.y, xr.y);
        Xs[p][xk + 2][xm] = pack2(xr.z, xr.z);
        Xs[p][xk + 3][xm] = pack2(xr.w, xr.w);
        #pragma unroll
        for (int q = 0; q < 4; ++q)
            *reinterpret_cast<float4*>(&Ws[p][wk + q * 4][wn]) = wr[q];
    };

    load_stage(kbase);
    commit(0);
    __syncthreads();

    int p = 0;
    for (int k0 = kbase; k0 < kbase + KSPLIT; k0 += BK) {
        const bool more = (k0 + BK) < (kbase + KSPLIT);
        if (more) load_stage(k0 + BK);
        #pragma unroll
        for (int kk = 0; kk < BK; ++kk) {
            unsigned long long am[4];
            #pragma unroll
            for (int i = 0; i < 4; ++i) am[i] = Xs[p][kk][tm + i];
            const ulonglong2 w0 = *reinterpret_cast<const ulonglong2*>(&Ws[p][kk][tn]);
            const ulonglong2 w1 = *reinterpret_cast<const ulonglong2*>(&Ws[p][kk][tn + 4]);
            const unsigned long long wv[4] = {w0.x, w0.y, w1.x, w1.y};
            #pragma unroll
            for (int i = 0; i < 4; ++i)
                #pragma unroll
                for (int j = 0; j < 4; ++j)
                    ffma2(acc[i][j], am[i], wv[j]);
        }
        if (more) commit(p ^ 1);
        __syncthreads();
        p ^= 1;
    }

    // epilogue: write split partials (reduce adds bias)
    float* pbase = g_partial + (size_t)split * kB * kOut;
    #pragma unroll
    for (int i = 0; i < 4; ++i) {
        const int r = srows[tm + i];
        if (r < 0) continue;
        float* prow = pbase + (size_t)r * kOut;
        #pragma unroll
        for (int j = 0; j < 4; ++j) {
            const int n = n0 + tn + 2 * j;
            if (n + 1 < kOut) {
                float lo, hi; unpack2(acc[i][j], lo, hi);
                *reinterpret_cast<float2*>(prow + n) = make_float2(lo, hi);
            } else if (n < kOut) {
                float lo, hi; unpack2(acc[i][j], lo, hi);
                prow[n] = lo;
            }
        }
    }
}

// ---------------------------------------------------------------------------
// Reduce: sum NSPLIT partials, add per-subject bias, float4 throughout.
// ---------------------------------------------------------------------------
__global__ __launch_bounds__(256) void reduce_kernel(
    const unsigned int* __restrict__ sid_words,
    const float* __restrict__ bias,   // [S, OUT]
    float* __restrict__ out)          // [B, OUT]
{
    __shared__ int i32_flag;
    if (threadIdx.x == 0) i32_flag = 0;
    __syncthreads();
    if (threadIdx.x < 128 && sid_words[2 * threadIdx.x + 1] != 0u)
        atomicOr(&i32_flag, 1);
    __syncthreads();

    const int q = blockIdx.x * blockDim.x + threadIdx.x;  // float4 index
    const int base = q * 4;
    if (base >= kB * kOut) return;
    const int b = base / kOut;
    const int n = base - b * kOut;    // kOut % 4 == 0: float4 stays in-row
    const int sb = i32_flag ? (int)sid_words[b] : (int)sid_words[2 * b];

    float4 v = *reinterpret_cast<const float4*>(bias + (size_t)sb * kOut + n);
    #pragma unroll
    for (int sp = 0; sp < NSPLIT; ++sp) {
        const float4 pv = *reinterpret_cast<const float4*>(
            g_partial + (size_t)sp * kB * kOut + base);
        v.x += pv.x; v.y += pv.y; v.z += pv.z; v.w += pv.w;
    }
    *reinterpret_cast<float4*>(out + base) = v;
}

extern "C" void kernel_launch(void* const* d_in, const int* in_sizes, int n_in,
                              void* d_out, int out_size) {
    const float*        x   = (const float*)d_in[0];
    const unsigned int* sid = (const unsigned int*)d_in[1];
    const float*        W   = (const float*)d_in[2];
    const float*        b   = (const float*)d_in[3];
    float*              out = (float*)d_out;

    dim3 grid(NTILES, kS, MT * NSPLIT);   // (8, 8, 32)
    gemm_kernel<<<grid, 128>>>(x, W, sid);
    const int nq = (kB * kOut) / 4;       // 64000
    reduce_kernel<<<(nq + 255) / 256, 256>>>(sid, b, out);
}